// round 14
// baseline (speedup 1.0000x reference)
#include <cuda_runtime.h>
#include <cuda_fp16.h>
#include <cstdint>

#define TOKENS   16384
#define HIDDEN   4096
#define EXPERTS  64

#define M_TILE   128
#define KC       64
#define NITER    (HIDDEN / KC)     // 64
#define NTHREADS 512
#define NSTAGE   5

// ---- shared memory layout ----
// per stage: A 16KB | B 8KB   (fp16)
#define STG_BYTES 24576
#define B_OFF     16384
#define SM_MBAR   8                       // full/empty pairs, 16B per stage
#define SM_SCALES 256
#define SM_STG    1024
#define SM_RED    (SM_STG + NSTAGE * STG_BYTES)   // 123904
#define SM_TOTAL  (SM_RED + 32768)                // 156672

// SW128 swizzle (Swizzle<3,4,3>)
#define SW(o) ((o) ^ (((o) >> 3) & 0x70))

// ---------------- helpers ----------------
__device__ __forceinline__ uint32_t smem_to_u32(const void* p) {
    uint32_t a;
    asm("{ .reg .u64 t; cvta.to.shared.u64 t, %1; cvt.u32.u64 %0, t; }" : "=r"(a) : "l"(p));
    return a;
}
__device__ __forceinline__ void sts64(uint32_t addr, uint32_t a, uint32_t b) {
    asm volatile("st.shared.v2.b32 [%0], {%1,%2};" :: "r"(addr), "r"(a), "r"(b) : "memory");
}
__device__ __forceinline__ void sts128(uint32_t addr, uint32_t a, uint32_t b,
                                       uint32_t c, uint32_t d) {
    asm volatile("st.shared.v4.b32 [%0], {%1,%2,%3,%4};"
                 :: "r"(addr), "r"(a), "r"(b), "r"(c), "r"(d) : "memory");
}
__device__ __forceinline__ void lds128f(float (&v)[4], uint32_t addr) {
    asm volatile("ld.shared.v4.f32 {%0,%1,%2,%3}, [%4];"
                 : "=f"(v[0]), "=f"(v[1]), "=f"(v[2]), "=f"(v[3]) : "r"(addr));
}
// pack_f16(lo, hi): low half-word = f16(lo), high = f16(hi)
__device__ __forceinline__ uint32_t pack_f16(float lo, float hi) {
    uint32_t r;
    asm("cvt.rn.f16x2.f32 %0, %1, %2;" : "=r"(r) : "f"(hi), "f"(lo));
    return r;
}
__device__ __forceinline__ void ldsm4(uint32_t (&r)[4], uint32_t addr) {
    asm volatile("ldmatrix.sync.aligned.m8n8.x4.shared.b16 {%0,%1,%2,%3}, [%4];"
                 : "=r"(r[0]), "=r"(r[1]), "=r"(r[2]), "=r"(r[3]) : "r"(addr));
}
__device__ __forceinline__ void mma16816(float (&d)[4], const uint32_t (&a)[4],
                                         uint32_t b0, uint32_t b1) {
    asm volatile("mma.sync.aligned.m16n8k16.row.col.f32.f16.f16.f32 "
                 "{%0,%1,%2,%3}, {%4,%5,%6,%7}, {%8,%9}, {%0,%1,%2,%3};"
                 : "+f"(d[0]), "+f"(d[1]), "+f"(d[2]), "+f"(d[3])
                 : "r"(a[0]), "r"(a[1]), "r"(a[2]), "r"(a[3]), "r"(b0), "r"(b1));
}

#define MBARRIER_INIT(mbar, count) \
    asm volatile("mbarrier.init.shared.b64 [%0], %1;" \
                 :: "r"((uint32_t)(mbar)), "r"((uint32_t)(count)) : "memory")
#define MBARRIER_ARRIVE(mbar) \
    asm volatile("mbarrier.arrive.shared.b64 _, [%0];" :: "r"((uint32_t)(mbar)) : "memory")
#define MBARRIER_WAIT_PARITY(mbar_smem_addr, phase_parity) do { \
    uint32_t _mbar = (uint32_t)(mbar_smem_addr); \
    uint32_t _parity = (uint32_t)(phase_parity); \
    uint32_t _done; \
    asm volatile("{\n\t.reg .pred p;\n\t" \
        "mbarrier.try_wait.parity.shared.b64 p, [%1], %2;\n\t" \
        "selp.b32 %0, 1, 0, p;\n\t}" \
        : "=r"(_done) : "r"(_mbar), "r"(_parity) : "memory"); \
    if (!_done) { \
        asm volatile("{\n\t.reg .pred P1;\n\t" \
            "WAIT_LOOP_%=:\n\t" \
            "mbarrier.try_wait.parity.shared.b64 P1, [%0], %1, 0x989680;\n\t" \
            "@P1 bra.uni WAIT_DONE_%=;\n\t" \
            "bra.uni WAIT_LOOP_%=;\n\t" \
            "WAIT_DONE_%=:\n\t}" \
            :: "r"(_mbar), "r"(_parity) : "memory"); \
    } \
} while (0)

// ---------------- kernel ----------------

struct ProdCtx {
    const float* xA;                 // base for A loads (row-pair stride 2*HIDDEN)
    const int*   wB;                 // base for B int32 loads
    uint32_t oAr0;                   // STS offset for j=0 (stride 256B per j)
    uint32_t oB;
};

__device__ __forceinline__ void prefetchA(const ProdCtx& c, int chunk, float4 (&a)[8]) {
#pragma unroll
    for (int j = 0; j < 8; j++)
        a[j] = *(const float4*)(c.xA + (size_t)(2 * j) * HIDDEN + chunk * KC);
}
// load B int32 and immediately convert to packed fp16 (8 regs, not 16).
// The cvt stalls on L2 latency here, where producers have ring slack.
__device__ __forceinline__ void prefetchB(const ProdCtx& c, int chunk, uint32_t (&h)[8]) {
    const int4* pb = (const int4*)(c.wB + chunk * KC);
#pragma unroll
    for (int j = 0; j < 4; j++) {
        int4 t = pb[j];
        h[2 * j]     = pack_f16((float)t.x, (float)t.y);
        h[2 * j + 1] = pack_f16((float)t.z, (float)t.w);
    }
}

__device__ __forceinline__ void prod_stage(const ProdCtx& c, const float4 (&a)[8],
                                           const uint32_t (&bh)[8], uint32_t stg) {
    const uint32_t AH = stg, BB = stg + B_OFF;
#pragma unroll
    for (int j = 0; j < 8; j++) {
        float4 f = a[j];
        uint32_t h0 = pack_f16(f.x, f.y);
        uint32_t h1 = pack_f16(f.z, f.w);
        sts64(AH + SW(c.oAr0 + (uint32_t)j * 256), h0, h1);
    }
    sts128(BB + SW(c.oB),      bh[0], bh[1], bh[2], bh[3]);
    sts128(BB + SW(c.oB + 16), bh[4], bh[5], bh[6], bh[7]);
}

__global__ void __launch_bounds__(NTHREADS, 1)
gemm_kernel(const float* __restrict__ x,
            const int* __restrict__ w,
            const float* __restrict__ scales,
            float* __restrict__ out) {
    extern __shared__ char smem[];
    const uint32_t sbase = smem_to_u32(smem);
    const int tid = threadIdx.x;
    const int wid = tid >> 5;
    const int lid = tid & 31;
    const int m0  = blockIdx.x * M_TILE;

    if (tid == 0) {
#pragma unroll
        for (int s = 0; s < NSTAGE; s++) {
            MBARRIER_INIT(sbase + SM_MBAR + s * 16,     8);   // full[s]: 8 producer warps
            MBARRIER_INIT(sbase + SM_MBAR + s * 16 + 8, 8);   // empty[s]: 8 consumer warps
        }
    }
    if (tid < EXPERTS) ((float*)(smem + SM_SCALES))[tid] = scales[tid];
    __syncthreads();

    if (wid < 8) {
        // ================= PRODUCER (warps 0-7) =================
        // A: warp w stages rows 16w..16w+15; LDG j covers rows (16w+2j, 16w+2j+1):
        //    thread -> row +lsub, 16B piece lcol => 4 cache lines per LDG.128.
        const int lsub = lid >> 4, lcol = lid & 15;
        ProdCtx c;
        c.xA   = x + (size_t)(m0 + 16 * wid + lsub) * HIDDEN + lcol * 4;
        c.oAr0 = (uint32_t)(16 * wid + lsub) * 128 + lcol * 8;
        // B: thread t (0..255) -> expert e=t>>2, 16-k quarter q=t&3 (int32 source)
        const int e = tid >> 2, q = tid & 3;
        c.wB = w + (size_t)e * HIDDEN + q * 16;
        c.oB = (uint32_t)e * 128 + q * 32;

        // ---- 2-deep STATIC register prefetch; B pre-converted to fp16 (8 regs/set)
        float4 a0[8], a1[8]; uint32_t bh0[8], bh1[8];
        prefetchA(c, 0, a0);
        prefetchA(c, 1, a1);
        prefetchB(c, 0, bh0);
        prefetchB(c, 1, bh1);

        int ps = 0, pph = 1;   // producer phase starts at 1: first empty-wait passes
#pragma unroll 1
        for (int i = 0; i < NITER; i += 2) {
            MBARRIER_WAIT_PARITY(sbase + SM_MBAR + ps * 16 + 8, pph);
            prod_stage(c, a0, bh0, sbase + SM_STG + ps * STG_BYTES);
            __syncwarp();
            if (lid == 0) MBARRIER_ARRIVE(sbase + SM_MBAR + ps * 16);
            if (++ps == NSTAGE) { ps = 0; pph ^= 1; }
            if (i + 2 < NITER) { prefetchA(c, i + 2, a0); prefetchB(c, i + 2, bh0); }

            MBARRIER_WAIT_PARITY(sbase + SM_MBAR + ps * 16 + 8, pph);
            prod_stage(c, a1, bh1, sbase + SM_STG + ps * STG_BYTES);
            __syncwarp();
            if (lid == 0) MBARRIER_ARRIVE(sbase + SM_MBAR + ps * 16);
            if (++ps == NSTAGE) { ps = 0; pph ^= 1; }
            if (i + 3 < NITER) { prefetchA(c, i + 3, a1); prefetchB(c, i + 3, bh1); }
        }
        __syncthreads();  // join tail
        __syncthreads();
    } else {
        // ================= CONSUMER (warps 8-15) =================
        // 8 warps = 4 row-groups x 2 k-split; warp = 32 rows x 64 experts x 32k
        const int cw = wid - 8;
        const int rg = cw & 3;
        const int kg = cw >> 2;

        uint32_t aRel[2][2], bRel[4][2];
#pragma unroll
        for (int mt = 0; mt < 2; mt++)
#pragma unroll
            for (int ks = 0; ks < 2; ks++)
                aRel[mt][ks] = (uint32_t)(32 * rg + 16 * mt + (lid & 15)) * 128
                             + (uint32_t)kg * 64 + (uint32_t)ks * 32
                             + (uint32_t)(lid >> 4) * 16;
#pragma unroll
        for (int nt = 0; nt < 4; nt++)
#pragma unroll
            for (int ks = 0; ks < 2; ks++)
                bRel[nt][ks] = (uint32_t)(16 * nt + (lid & 7) + ((lid >> 4) << 3)) * 128
                             + (uint32_t)kg * 64 + (uint32_t)ks * 32
                             + (uint32_t)((lid >> 3) & 1) * 16;

        float acc[2][8][4];
#pragma unroll
        for (int mt = 0; mt < 2; mt++)
#pragma unroll
            for (int nt = 0; nt < 8; nt++)
#pragma unroll
                for (int j = 0; j < 4; j++) acc[mt][nt][j] = 0.0f;

        int cs = 0, cph = 0;
#pragma unroll 1
        for (int i = 0; i < NITER; i++) {
            MBARRIER_WAIT_PARITY(sbase + SM_MBAR + cs * 16, cph);
            const uint32_t stg = sbase + SM_STG + cs * STG_BYTES;
            const uint32_t AH = stg, BB = stg + B_OFF;
#pragma unroll
            for (int ks = 0; ks < 2; ks++) {
                uint32_t ah[2][4];
                ldsm4(ah[0], AH + SW(aRel[0][ks]));
                ldsm4(ah[1], AH + SW(aRel[1][ks]));
#pragma unroll
                for (int nt = 0; nt < 4; nt++) {
                    uint32_t bb[4];
                    ldsm4(bb, BB + SW(bRel[nt][ks]));
#pragma unroll
                    for (int mt = 0; mt < 2; mt++) {
                        mma16816(acc[mt][2 * nt],     ah[mt], bb[0], bb[1]);
                        mma16816(acc[mt][2 * nt + 1], ah[mt], bb[2], bb[3]);
                    }
                }
            }
            __syncwarp();
            if (lid == 0) MBARRIER_ARRIVE(sbase + SM_MBAR + cs * 16 + 8);
            if (++cs == NSTAGE) { cs = 0; cph ^= 1; }
        }

        // ---- k-split fold: kg=1 dumps, kg=0 adds + writes
        const uint32_t redW = sbase + SM_RED + (uint32_t)rg * 8192;
        if (kg == 1) {
#pragma unroll
            for (int mt = 0; mt < 2; mt++)
#pragma unroll
                for (int nt = 0; nt < 8; nt++)
                    sts128(redW + (uint32_t)(mt * 8 + nt) * 512 + (uint32_t)lid * 16,
                           __float_as_uint(acc[mt][nt][0]), __float_as_uint(acc[mt][nt][1]),
                           __float_as_uint(acc[mt][nt][2]), __float_as_uint(acc[mt][nt][3]));
        }
        __syncthreads();
        if (kg == 0) {
            const float* sc = (const float*)(smem + SM_SCALES);
            const int cq = 2 * (lid & 3);
#pragma unroll
            for (int mt = 0; mt < 2; mt++) {
                const int rbase = m0 + 32 * rg + 16 * mt + (lid >> 2);
#pragma unroll
                for (int nt = 0; nt < 8; nt++) {
                    float u[4];
                    lds128f(u, redW + (uint32_t)(mt * 8 + nt) * 512 + (uint32_t)lid * 16);
                    const int c0 = 8 * nt + cq;
                    const float s0 = sc[c0], s1 = sc[c0 + 1];
                    float2 v0 = make_float2((acc[mt][nt][0] + u[0]) * s0,
                                            (acc[mt][nt][1] + u[1]) * s1);
                    float2 v1 = make_float2((acc[mt][nt][2] + u[2]) * s0,
                                            (acc[mt][nt][3] + u[3]) * s1);
                    *(float2*)(out + (size_t)rbase * EXPERTS + c0)       = v0;
                    *(float2*)(out + (size_t)(rbase + 8) * EXPERTS + c0) = v1;
                }
            }
        }
        __syncthreads();
    }
}

extern "C" void kernel_launch(void* const* d_in, const int* in_sizes, int n_in,
                              void* d_out, int out_size) {
    const float* x      = (const float*)d_in[0];
    const int*   w      = (const int*)d_in[1];
    const float* scales = (const float*)d_in[2];
    float* out = (float*)d_out;

    cudaFuncSetAttribute(gemm_kernel, cudaFuncAttributeMaxDynamicSharedMemorySize, SM_TOTAL);

    gemm_kernel<<<TOKENS / M_TILE, NTHREADS, SM_TOTAL>>>(x, w, scales, out);
}

// round 15
// speedup vs baseline: 1.0979x; 1.0979x over previous
#include <cuda_runtime.h>
#include <cuda_fp16.h>
#include <cstdint>

#define TOKENS   16384
#define HIDDEN   4096
#define EXPERTS  64

#define M_TILE   128
#define KC       64
#define NITER    (HIDDEN / KC)     // 64
#define NTHREADS 512
#define NSTAGE   5

// ---- shared memory layout ----
// per stage: A 16KB | B 8KB   (fp16)
#define STG_BYTES 24576
#define B_OFF     16384
#define SM_MBAR   8                       // full/empty pairs, 16B per stage
#define SM_SCALES 256
#define SM_STG    1024
#define SM_RED    (SM_STG + NSTAGE * STG_BYTES)   // 123904
#define SM_TOTAL  (SM_RED + 32768)                // 156672

// SW128 swizzle (Swizzle<3,4,3>)
#define SW(o) ((o) ^ (((o) >> 3) & 0x70))

// weights as fp16 (int8 values exact in fp16; scale folded into epilogue)
__device__ __half g_wh[EXPERTS * HIDDEN];

// ---------------- helpers ----------------
__device__ __forceinline__ uint32_t smem_to_u32(const void* p) {
    uint32_t a;
    asm("{ .reg .u64 t; cvta.to.shared.u64 t, %1; cvt.u32.u64 %0, t; }" : "=r"(a) : "l"(p));
    return a;
}
__device__ __forceinline__ void sts64(uint32_t addr, uint32_t a, uint32_t b) {
    asm volatile("st.shared.v2.b32 [%0], {%1,%2};" :: "r"(addr), "r"(a), "r"(b) : "memory");
}
__device__ __forceinline__ void sts128(uint32_t addr, uint32_t a, uint32_t b,
                                       uint32_t c, uint32_t d) {
    asm volatile("st.shared.v4.b32 [%0], {%1,%2,%3,%4};"
                 :: "r"(addr), "r"(a), "r"(b), "r"(c), "r"(d) : "memory");
}
__device__ __forceinline__ void lds128f(float (&v)[4], uint32_t addr) {
    asm volatile("ld.shared.v4.f32 {%0,%1,%2,%3}, [%4];"
                 : "=f"(v[0]), "=f"(v[1]), "=f"(v[2]), "=f"(v[3]) : "r"(addr));
}
// pack_f16(lo, hi): low half-word = f16(lo), high = f16(hi)
__device__ __forceinline__ uint32_t pack_f16(float lo, float hi) {
    uint32_t r;
    asm("cvt.rn.f16x2.f32 %0, %1, %2;" : "=r"(r) : "f"(hi), "f"(lo));
    return r;
}
__device__ __forceinline__ void ldsm4(uint32_t (&r)[4], uint32_t addr) {
    asm volatile("ldmatrix.sync.aligned.m8n8.x4.shared.b16 {%0,%1,%2,%3}, [%4];"
                 : "=r"(r[0]), "=r"(r[1]), "=r"(r[2]), "=r"(r[3]) : "r"(addr));
}
__device__ __forceinline__ void mma16816(float (&d)[4], const uint32_t (&a)[4],
                                         uint32_t b0, uint32_t b1) {
    asm volatile("mma.sync.aligned.m16n8k16.row.col.f32.f16.f16.f32 "
                 "{%0,%1,%2,%3}, {%4,%5,%6,%7}, {%8,%9}, {%0,%1,%2,%3};"
                 : "+f"(d[0]), "+f"(d[1]), "+f"(d[2]), "+f"(d[3])
                 : "r"(a[0]), "r"(a[1]), "r"(a[2]), "r"(a[3]), "r"(b0), "r"(b1));
}

#define MBARRIER_INIT(mbar, count) \
    asm volatile("mbarrier.init.shared.b64 [%0], %1;" \
                 :: "r"((uint32_t)(mbar)), "r"((uint32_t)(count)) : "memory")
#define MBARRIER_ARRIVE(mbar) \
    asm volatile("mbarrier.arrive.shared.b64 _, [%0];" :: "r"((uint32_t)(mbar)) : "memory")
#define MBARRIER_WAIT_PARITY(mbar_smem_addr, phase_parity) do { \
    uint32_t _mbar = (uint32_t)(mbar_smem_addr); \
    uint32_t _parity = (uint32_t)(phase_parity); \
    uint32_t _done; \
    asm volatile("{\n\t.reg .pred p;\n\t" \
        "mbarrier.try_wait.parity.shared.b64 p, [%1], %2;\n\t" \
        "selp.b32 %0, 1, 0, p;\n\t}" \
        : "=r"(_done) : "r"(_mbar), "r"(_parity) : "memory"); \
    if (!_done) { \
        asm volatile("{\n\t.reg .pred P1;\n\t" \
            "WAIT_LOOP_%=:\n\t" \
            "mbarrier.try_wait.parity.shared.b64 P1, [%0], %1, 0x989680;\n\t" \
            "@P1 bra.uni WAIT_DONE_%=;\n\t" \
            "bra.uni WAIT_LOOP_%=;\n\t" \
            "WAIT_DONE_%=:\n\t}" \
            :: "r"(_mbar), "r"(_parity) : "memory"); \
    } \
} while (0)

// ---------------- kernels ----------------

__global__ void dequant_kernel(const int* __restrict__ w) {
    int t = blockIdx.x * blockDim.x + threadIdx.x;        // 0..65535, 4 weights each
    int4 v = ((const int4*)w)[t];
    uint2 p;
    p.x = pack_f16((float)v.x, (float)v.y);
    p.y = pack_f16((float)v.z, (float)v.w);
    ((uint2*)g_wh)[t] = p;
}

struct ProdCtx {
    const float* xA;                 // base for A loads (row-pair stride 2*HIDDEN)
    const __half* wpB;               // base for B loads
    uint32_t oAr0;                   // STS offset for j=0 (stride 256B per j)
    uint32_t oB;
};

__device__ __forceinline__ void prod_prefetch(const ProdCtx& c, int chunk,
                                              float4 (&a)[8], uint4 (&b)[2]) {
#pragma unroll
    for (int j = 0; j < 8; j++)
        a[j] = *(const float4*)(c.xA + (size_t)(2 * j) * HIDDEN + chunk * KC);
    const uint4* pb = (const uint4*)(c.wpB + chunk * KC);
    b[0] = pb[0]; b[1] = pb[1];
}

__device__ __forceinline__ void prod_stage(const ProdCtx& c, const float4 (&a)[8],
                                           const uint4 (&b)[2], uint32_t stg) {
    const uint32_t AH = stg, BB = stg + B_OFF;
#pragma unroll
    for (int j = 0; j < 8; j++) {
        float4 f = a[j];
        uint32_t h0 = pack_f16(f.x, f.y);
        uint32_t h1 = pack_f16(f.z, f.w);
        sts64(AH + SW(c.oAr0 + (uint32_t)j * 256), h0, h1);
    }
    sts128(BB + SW(c.oB),      b[0].x, b[0].y, b[0].z, b[0].w);
    sts128(BB + SW(c.oB + 16), b[1].x, b[1].y, b[1].z, b[1].w);
}

__global__ void __launch_bounds__(NTHREADS, 1)
gemm_kernel(const float* __restrict__ x,
            const float* __restrict__ scales,
            float* __restrict__ out) {
    extern __shared__ char smem[];
    const uint32_t sbase = smem_to_u32(smem);
    const int tid = threadIdx.x;
    const int wid = tid >> 5;
    const int lid = tid & 31;
    const int m0  = blockIdx.x * M_TILE;

    if (tid == 0) {
#pragma unroll
        for (int s = 0; s < NSTAGE; s++) {
            MBARRIER_INIT(sbase + SM_MBAR + s * 16,     8);   // full[s]: 8 producer warps
            MBARRIER_INIT(sbase + SM_MBAR + s * 16 + 8, 8);   // empty[s]: 8 consumer warps
        }
    }
    if (tid < EXPERTS) ((float*)(smem + SM_SCALES))[tid] = scales[tid];
    __syncthreads();

    if (wid < 8) {
        // ================= PRODUCER (warps 0-7) =================
        // A: warp w stages rows 16w..16w+15; LDG j covers rows (16w+2j, 16w+2j+1):
        //    thread -> row +lsub, 16B piece lcol => 4 cache lines per LDG.128.
        const int lsub = lid >> 4, lcol = lid & 15;
        ProdCtx c;
        c.xA   = x + (size_t)(m0 + 16 * wid + lsub) * HIDDEN + lcol * 4;
        c.oAr0 = (uint32_t)(16 * wid + lsub) * 128 + lcol * 8;
        // B: thread t (0..255) -> expert e=t>>2, 32B piece p=t&3
        const int e = tid >> 2, p = tid & 3;
        c.wpB = g_wh + (size_t)e * HIDDEN + p * 16;
        c.oB  = (uint32_t)e * 128 + p * 32;

        float4 a0[8], a1[8]; uint4 b0[2], b1[2];
        prod_prefetch(c, 0, a0, b0);
        prod_prefetch(c, 1, a1, b1);

        int ps = 0, pph = 1;   // producer phase starts at 1: first empty-wait passes
#pragma unroll 1
        for (int i = 0; i < NITER; i += 2) {
            MBARRIER_WAIT_PARITY(sbase + SM_MBAR + ps * 16 + 8, pph);
            prod_stage(c, a0, b0, sbase + SM_STG + ps * STG_BYTES);
            __syncwarp();
            if (lid == 0) MBARRIER_ARRIVE(sbase + SM_MBAR + ps * 16);
            if (++ps == NSTAGE) { ps = 0; pph ^= 1; }
            if (i + 2 < NITER) prod_prefetch(c, i + 2, a0, b0);

            MBARRIER_WAIT_PARITY(sbase + SM_MBAR + ps * 16 + 8, pph);
            prod_stage(c, a1, b1, sbase + SM_STG + ps * STG_BYTES);
            __syncwarp();
            if (lid == 0) MBARRIER_ARRIVE(sbase + SM_MBAR + ps * 16);
            if (++ps == NSTAGE) { ps = 0; pph ^= 1; }
            if (i + 3 < NITER) prod_prefetch(c, i + 3, a1, b1);
        }
        __syncthreads();  // join tail
        __syncthreads();
    } else {
        // ================= CONSUMER (warps 8-15) =================
        // 8 warps = 4 row-groups x 2 k-split; warp = 32 rows x 64 experts x 32k
        const int cw = wid - 8;
        const int rg = cw & 3;
        const int kg = cw >> 2;

        uint32_t aRel[2][2], bRel[4][2];
#pragma unroll
        for (int mt = 0; mt < 2; mt++)
#pragma unroll
            for (int ks = 0; ks < 2; ks++)
                aRel[mt][ks] = (uint32_t)(32 * rg + 16 * mt + (lid & 15)) * 128
                             + (uint32_t)kg * 64 + (uint32_t)ks * 32
                             + (uint32_t)(lid >> 4) * 16;
#pragma unroll
        for (int nt = 0; nt < 4; nt++)
#pragma unroll
            for (int ks = 0; ks < 2; ks++)
                bRel[nt][ks] = (uint32_t)(16 * nt + (lid & 7) + ((lid >> 4) << 3)) * 128
                             + (uint32_t)kg * 64 + (uint32_t)ks * 32
                             + (uint32_t)((lid >> 3) & 1) * 16;

        float acc[2][8][4];
#pragma unroll
        for (int mt = 0; mt < 2; mt++)
#pragma unroll
            for (int nt = 0; nt < 8; nt++)
#pragma unroll
                for (int j = 0; j < 4; j++) acc[mt][nt][j] = 0.0f;

        int cs = 0, cph = 0;
#pragma unroll 1
        for (int i = 0; i < NITER; i++) {
            MBARRIER_WAIT_PARITY(sbase + SM_MBAR + cs * 16, cph);
            const uint32_t stg = sbase + SM_STG + cs * STG_BYTES;
            const uint32_t AH = stg, BB = stg + B_OFF;
#pragma unroll
            for (int ks = 0; ks < 2; ks++) {
                uint32_t ah[2][4];
                ldsm4(ah[0], AH + SW(aRel[0][ks]));
                ldsm4(ah[1], AH + SW(aRel[1][ks]));
#pragma unroll
                for (int nt = 0; nt < 4; nt++) {
                    uint32_t bb[4];
                    ldsm4(bb, BB + SW(bRel[nt][ks]));
#pragma unroll
                    for (int mt = 0; mt < 2; mt++) {
                        mma16816(acc[mt][2 * nt],     ah[mt], bb[0], bb[1]);
                        mma16816(acc[mt][2 * nt + 1], ah[mt], bb[2], bb[3]);
                    }
                }
            }
            __syncwarp();
            if (lid == 0) MBARRIER_ARRIVE(sbase + SM_MBAR + cs * 16 + 8);
            if (++cs == NSTAGE) { cs = 0; cph ^= 1; }
        }

        // ---- k-split fold: kg=1 dumps, kg=0 adds + writes
        const uint32_t redW = sbase + SM_RED + (uint32_t)rg * 8192;
        if (kg == 1) {
#pragma unroll
            for (int mt = 0; mt < 2; mt++)
#pragma unroll
                for (int nt = 0; nt < 8; nt++)
                    sts128(redW + (uint32_t)(mt * 8 + nt) * 512 + (uint32_t)lid * 16,
                           __float_as_uint(acc[mt][nt][0]), __float_as_uint(acc[mt][nt][1]),
                           __float_as_uint(acc[mt][nt][2]), __float_as_uint(acc[mt][nt][3]));
        }
        __syncthreads();
        if (kg == 0) {
            const float* sc = (const float*)(smem + SM_SCALES);
            const int cq = 2 * (lid & 3);
#pragma unroll
            for (int mt = 0; mt < 2; mt++) {
                const int rbase = m0 + 32 * rg + 16 * mt + (lid >> 2);
#pragma unroll
                for (int nt = 0; nt < 8; nt++) {
                    float u[4];
                    lds128f(u, redW + (uint32_t)(mt * 8 + nt) * 512 + (uint32_t)lid * 16);
                    const int c0 = 8 * nt + cq;
                    const float s0 = sc[c0], s1 = sc[c0 + 1];
                    float2 v0 = make_float2((acc[mt][nt][0] + u[0]) * s0,
                                            (acc[mt][nt][1] + u[1]) * s1);
                    float2 v1 = make_float2((acc[mt][nt][2] + u[2]) * s0,
                                            (acc[mt][nt][3] + u[3]) * s1);
                    *(float2*)(out + (size_t)rbase * EXPERTS + c0)       = v0;
                    *(float2*)(out + (size_t)(rbase + 8) * EXPERTS + c0) = v1;
                }
            }
        }
        __syncthreads();
    }
}

extern "C" void kernel_launch(void* const* d_in, const int* in_sizes, int n_in,
                              void* d_out, int out_size) {
    const float* x      = (const float*)d_in[0];
    const int*   w      = (const int*)d_in[1];
    const float* scales = (const float*)d_in[2];
    float* out = (float*)d_out;

    cudaFuncSetAttribute(gemm_kernel, cudaFuncAttributeMaxDynamicSharedMemorySize, SM_TOTAL);

    dequant_kernel<<<256, 256>>>(w);                 // int32 weights -> fp16 (exact), once
    gemm_kernel<<<TOKENS / M_TILE, NTHREADS, SM_TOTAL>>>(x, scales, out);
}